// round 13
// baseline (speedup 1.0000x reference)
#include <cuda_runtime.h>
#include <cstdint>

// Problem constants
#define B_   4
#define C_   64
#define HL   64      // low-res h = w
#define HH   256     // high-res H = W
#define NPIX (HH*HH)
#define GN   (3*HH*HH)
#define INV2SS2 0.08f        // 1/(2*2.5^2)

#define ROWP 101             // padded pos stride (float4 units) per channel plane

// dynamic smem layout (floats):
//   s_src: 16 planes * ROWP * 4      = 6464
//   s_w  : 25 taps  * 64 col * 4 r   = 6400
//   s_gl : 3 * 5 * 20                = 300
//   s_inv: 1
#define OFF_W   6464
#define OFF_GL  12864
#define OFF_INV 13164
#define SMEM_BYTES ((OFF_INV + 4) * 4)   // 52672 B

// ---------------- scratch ----------------
__device__ float g_part[B_][64][2];          // per-block partial (sum, sumsq)

// ---------------- pre-pass: guidance sum/sumsq partials ----------------
__global__ __launch_bounds__(256) void jbu_pre(const float* __restrict__ guid) {
    const int b   = blockIdx.y;
    const int tid = threadIdx.x;
    const float* p = guid + (size_t)b * GN + (size_t)blockIdx.x * (GN / 64);
    float s = 0.f, s2 = 0.f;
    for (int i = tid; i < GN / 64; i += 256) {
        float v = p[i];
        s += v; s2 += v * v;
    }
    #pragma unroll
    for (int o = 16; o; o >>= 1) {
        s  += __shfl_xor_sync(0xffffffffu, s,  o);
        s2 += __shfl_xor_sync(0xffffffffu, s2, o);
    }
    __shared__ float sh[8][2];
    const int w = tid >> 5;
    if ((tid & 31) == 0) { sh[w][0] = s; sh[w][1] = s2; }
    __syncthreads();
    if (tid == 0) {
        float ts = 0.f, ts2 = 0.f;
        #pragma unroll
        for (int i = 0; i < 8; i++) { ts += sh[i][0]; ts2 += sh[i][1]; }
        g_part[b][blockIdx.x][0] = ts;
        g_part[b][blockIdx.x][1] = ts2;
    }
}

// ---------------- main JBU kernel ----------------
// Block: 256 threads, output tile = 4 rows x 64 cols (16 low-res cells).
// Grid: (HH/64=4, HH/4=64, B)
// __launch_bounds__(256, 4): cap regs at 64 so 4 CTAs/SM fit (occ 50%).
__global__ __launch_bounds__(256, 4) void jbu_main(
    const float* __restrict__ guid,   // (4,3,256,256)
    const float* __restrict__ src,    // (4,64,64,64) raw channel-major
    float* __restrict__ out)          // (4,64,256,256)
{
    extern __shared__ __align__(16) float smem[];
    float* s_src = smem;              // [plane(16)][pos(ROWP)] float4-interleaved
    float* s_w   = smem + OFF_W;      // [tap(25)][col(64)][r(4)]
    float* s_gl  = smem + OFF_GL;     // [c(3)][dy(5)][xl(20)]
    float* s_inv = smem + OFF_INV;

    const int b     = blockIdx.z;
    const int cellY = blockIdx.y;         // 0..63
    const int cx0   = blockIdx.x * 16;    // first low-res cell x
    const int x0    = cx0 * 4;

    const int tid = threadIdx.x;

    // ---- stage source tile straight from raw gmem ----
    for (int i = tid; i < 6400; i += 256) {
        int c   = i / 100;
        int pos = i - c * 100;
        int yl  = pos / 20, xl = pos - yl * 20;
        int yi  = min(max(cellY + yl - 2, 0), HL - 1);
        int xi  = min(max(cx0   + xl - 2, 0), HL - 1);
        float v = src[(((size_t)b * C_ + c) * HL + yi) * HL + xi];
        s_src[(((c >> 2) * ROWP) + pos) * 4 + (c & 3)] = v;
    }

    // ---- stage g_low tile ----
    for (int i = tid; i < 300; i += 256) {
        int c  = i / 100;
        int rm = i - c * 100;
        int yl = rm / 20, xl = rm - yl * 20;
        int yi = min(max(cellY + yl - 2, 0), HL - 1);
        int xi = min(max(cx0   + xl - 2, 0), HL - 1);
        s_gl[(c * 5 + yl) * 20 + xl] =
            guid[(((size_t)b * 3 + c) * HH + (4 * yi + 2)) * HH + (4 * xi + 2)];
    }

    // ---- sigma finalization (warp 0, deterministic double shfl-tree) ----
    if (tid < 32) {
        double s  = (double)g_part[b][2 * tid][0] + (double)g_part[b][2 * tid + 1][0];
        double s2 = (double)g_part[b][2 * tid][1] + (double)g_part[b][2 * tid + 1][1];
        #pragma unroll
        for (int o = 16; o; o >>= 1) {
            s  += __shfl_xor_sync(0xffffffffu, s,  o);
            s2 += __shfl_xor_sync(0xffffffffu, s2, o);
        }
        if (tid == 0) {
            const double N = (double)GN;
            double var = (s2 - s * s / N) / (N - 1.0);
            s_inv[0] = (float)(2.0 / var);   // 1/(2*(0.5*sigma)^2) = 2/var
        }
    }
    __syncthreads();

    // ---- phase 1: per-pixel weights -> s_w[tap][col][r] ----
    {
        const int r   = tid >> 6;        // 0..3
        const int col = tid & 63;        // 0..63
        const int y   = cellY * 4 + r;
        const int x   = x0 + col;
        const int clx = col >> 2;
        const float inv2sr2 = s_inv[0];

        const float g0 = guid[(((size_t)b * 3 + 0) * HH + y) * HH + x];
        const float g1 = guid[(((size_t)b * 3 + 1) * HH + y) * HH + x];
        const float g2 = guid[(((size_t)b * 3 + 2) * HH + y) * HH + x];

        float w[25];
        float den = 0.f;
        #pragma unroll
        for (int dy = 0; dy < 5; dy++) {
            #pragma unroll
            for (int dx = 0; dx < 5; dx++) {
                const int t  = dy * 5 + dx;
                const int xl = clx + dx;
                float d0 = g0 - s_gl[(0 * 5 + dy) * 20 + xl];
                float d1 = g1 - s_gl[(1 * 5 + dy) * 20 + xl];
                float d2 = g2 - s_gl[(2 * 5 + dy) * 20 + xl];
                float diff2 = d0 * d0 + d1 * d1 + d2 * d2;
                float sp2 = (float)((dy - 2) * (dy - 2) + (dx - 2) * (dx - 2));
                float wt = __expf(-sp2 * INV2SS2 - diff2 * inv2sr2);
                w[t]  = wt;
                den  += wt;
            }
        }
        const float invden = 1.0f / (den + 1e-8f);
        #pragma unroll
        for (int t = 0; t < 25; t++)
            s_w[(t * 64 + col) * 4 + r] = w[t] * invden;
    }
    __syncthreads();

    // ---- phase 2: thread = (cgrp, col): 4 pixels (rows) x 16 channels ----
    const int cgrp = tid >> 6;           // 0..3 channel group
    const int col  = tid & 63;
    const int cell = col >> 2;
    const int x    = x0 + col;
    const int yb   = cellY * 4;

    const ulonglong2* wq = (const ulonglong2*)s_w + col;   // entry [t][col] at wq[t*64]

    #pragma unroll 1
    for (int c4i = 0; c4i < 4; c4i++) {
        const int plane = cgrp * 4 + c4i;
        const float4* ps = (const float4*)s_src + plane * ROWP + cell;

        // accA[c] = {out(r0,ch c), out(r1,ch c)}; accB[c] = rows 2,3
        unsigned long long accA0 = 0ULL, accA1 = 0ULL, accA2 = 0ULL, accA3 = 0ULL;
        unsigned long long accB0 = 0ULL, accB1 = 0ULL, accB2 = 0ULL, accB3 = 0ULL;

        #pragma unroll
        for (int dy = 0; dy < 5; dy++) {
            #pragma unroll
            for (int dx = 0; dx < 5; dx++) {
                const int t = dy * 5 + dx;
                ulonglong2 wv = wq[t * 64];          // {w_r0,w_r1},{w_r2,w_r3}
                float4 sv = ps[dy * 20 + dx];        // 4 channels
                unsigned long long ss0, ss1, ss2, ss3;
                asm("mov.b64 %0, {%1, %1};" : "=l"(ss0) : "f"(sv.x));
                asm("mov.b64 %0, {%1, %1};" : "=l"(ss1) : "f"(sv.y));
                asm("mov.b64 %0, {%1, %1};" : "=l"(ss2) : "f"(sv.z));
                asm("mov.b64 %0, {%1, %1};" : "=l"(ss3) : "f"(sv.w));
                asm("fma.rn.f32x2 %0, %1, %2, %0;" : "+l"(accA0) : "l"(wv.x), "l"(ss0));
                asm("fma.rn.f32x2 %0, %1, %2, %0;" : "+l"(accA1) : "l"(wv.x), "l"(ss1));
                asm("fma.rn.f32x2 %0, %1, %2, %0;" : "+l"(accA2) : "l"(wv.x), "l"(ss2));
                asm("fma.rn.f32x2 %0, %1, %2, %0;" : "+l"(accA3) : "l"(wv.x), "l"(ss3));
                asm("fma.rn.f32x2 %0, %1, %2, %0;" : "+l"(accB0) : "l"(wv.y), "l"(ss0));
                asm("fma.rn.f32x2 %0, %1, %2, %0;" : "+l"(accB1) : "l"(wv.y), "l"(ss1));
                asm("fma.rn.f32x2 %0, %1, %2, %0;" : "+l"(accB2) : "l"(wv.y), "l"(ss2));
                asm("fma.rn.f32x2 %0, %1, %2, %0;" : "+l"(accB3) : "l"(wv.y), "l"(ss3));
            }
        }

        // store 16 outputs: channels plane*4+c, rows yb..yb+3
        #pragma unroll
        for (int c = 0; c < 4; c++) {
            unsigned long long pa = (c == 0) ? accA0 : (c == 1) ? accA1 : (c == 2) ? accA2 : accA3;
            unsigned long long pb = (c == 0) ? accB0 : (c == 1) ? accB1 : (c == 2) ? accB2 : accB3;
            const int ch = plane * 4 + c;
            float* obase = out + ((((size_t)(b * C_ + ch)) * HH + yb) * HH) + x;
            float r0, r1, r2, r3;
            asm("mov.b64 {%0, %1}, %2;" : "=f"(r0), "=f"(r1) : "l"(pa));
            asm("mov.b64 {%0, %1}, %2;" : "=f"(r2), "=f"(r3) : "l"(pb));
            obase[0 * HH] = r0;
            obase[1 * HH] = r1;
            obase[2 * HH] = r2;
            obase[3 * HH] = r3;
        }
    }
}

// ---------------- launch ----------------
extern "C" void kernel_launch(void* const* d_in, const int* in_sizes, int n_in,
                              void* d_out, int out_size) {
    const float* src  = (const float*)d_in[0];
    const float* guid = (const float*)d_in[1];
    if (n_in >= 2 && in_sizes[0] == B_ * GN) {
        const float* tmp = src; src = guid; guid = tmp;
    }
    float* out = (float*)d_out;

    cudaFuncSetAttribute(jbu_main, cudaFuncAttributeMaxDynamicSharedMemorySize, SMEM_BYTES);

    jbu_pre<<<dim3(64, B_), 256>>>(guid);
    jbu_main<<<dim3(HH / 64, HH / 4, B_), 256, SMEM_BYTES>>>(guid, src, out);
}

// round 14
// speedup vs baseline: 1.6214x; 1.6214x over previous
#include <cuda_runtime.h>
#include <cstdint>

// Problem constants
#define B_   4
#define C_   64
#define HL   64      // low-res h = w
#define HH   256     // high-res H = W
#define NPIX (HH*HH)
#define GN   (3*HH*HH)
#define INV2SS2 0.08f        // 1/(2*2.5^2)

#define ROWP 101             // padded pos stride (float4 units) per channel plane

// ---------------- scratch ----------------
__device__ float g_part[B_][64][2];          // per-block partial (sum, sumsq)

// ---------------- pre-pass: guidance sum/sumsq partials ----------------
__global__ __launch_bounds__(256) void jbu_pre(const float* __restrict__ guid) {
    const int b   = blockIdx.y;
    const int tid = threadIdx.x;
    const float* p = guid + (size_t)b * GN + (size_t)blockIdx.x * (GN / 64);
    float s = 0.f, s2 = 0.f;
    for (int i = tid; i < GN / 64; i += 256) {
        float v = p[i];
        s += v; s2 += v * v;
    }
    #pragma unroll
    for (int o = 16; o; o >>= 1) {
        s  += __shfl_xor_sync(0xffffffffu, s,  o);
        s2 += __shfl_xor_sync(0xffffffffu, s2, o);
    }
    __shared__ float sh[8][2];
    const int w = tid >> 5;
    if ((tid & 31) == 0) { sh[w][0] = s; sh[w][1] = s2; }
    __syncthreads();
    if (tid == 0) {
        float ts = 0.f, ts2 = 0.f;
        #pragma unroll
        for (int i = 0; i < 8; i++) { ts += sh[i][0]; ts2 += sh[i][1]; }
        g_part[b][blockIdx.x][0] = ts;
        g_part[b][blockIdx.x][1] = ts2;
    }
}

// ---------------- main JBU kernel ----------------
// Block: 128 threads = (rp 0..1, col 0..63). Thread: 2 pixels (rows 2rp,2rp+1) x 64 ch.
// Tile: 4 rows x 64 cols (16 low-res cells). Grid: (HH/64=4, HH/4=64, B)
// launch_bounds(128,6): reg cap 85 — fits the true live set (25 packed weights + loop body).
__global__ __launch_bounds__(128, 6) void jbu_main(
    const float* __restrict__ guid,   // (4,3,256,256)
    const float* __restrict__ src,    // (4,64,64,64) raw channel-major
    float* __restrict__ out)          // (4,64,256,256)
{
    __shared__ __align__(16) float s_src[16 * ROWP * 4];   // [plane][pos] f4-interleaved, 25.9 KB
    __shared__ float s_gl[3][5][20];
    __shared__ float s_inv;

    const int b     = blockIdx.z;
    const int cellY = blockIdx.y;         // 0..63
    const int cx0   = blockIdx.x * 16;    // first low-res cell x
    const int x0    = cx0 * 4;

    const int tid = threadIdx.x;

    // ---- stage source tile straight from raw gmem ----
    for (int i = tid; i < 6400; i += 128) {
        int c   = i / 100;
        int pos = i - c * 100;
        int yl  = pos / 20, xl = pos - yl * 20;
        int yi  = min(max(cellY + yl - 2, 0), HL - 1);
        int xi  = min(max(cx0   + xl - 2, 0), HL - 1);
        float v = src[(((size_t)b * C_ + c) * HL + yi) * HL + xi];
        s_src[(((c >> 2) * ROWP) + pos) * 4 + (c & 3)] = v;
    }

    // ---- stage g_low tile ----
    for (int i = tid; i < 300; i += 128) {
        int c  = i / 100;
        int rm = i - c * 100;
        int yl = rm / 20, xl = rm - yl * 20;
        int yi = min(max(cellY + yl - 2, 0), HL - 1);
        int xi = min(max(cx0   + xl - 2, 0), HL - 1);
        s_gl[c][yl][xl] =
            guid[(((size_t)b * 3 + c) * HH + (4 * yi + 2)) * HH + (4 * xi + 2)];
    }

    // ---- sigma finalization (warp 0, deterministic double shfl-tree) ----
    if (tid < 32) {
        double s  = (double)g_part[b][2 * tid][0] + (double)g_part[b][2 * tid + 1][0];
        double s2 = (double)g_part[b][2 * tid][1] + (double)g_part[b][2 * tid + 1][1];
        #pragma unroll
        for (int o = 16; o; o >>= 1) {
            s  += __shfl_xor_sync(0xffffffffu, s,  o);
            s2 += __shfl_xor_sync(0xffffffffu, s2, o);
        }
        if (tid == 0) {
            const double N = (double)GN;
            double var = (s2 - s * s / N) / (N - 1.0);
            s_inv = (float)(2.0 / var);   // 1/(2*(0.5*sigma)^2) = 2/var
        }
    }
    __syncthreads();

    // ---- phase 1: weights for BOTH rows of this thread (kept in registers) ----
    const int rp   = tid >> 6;        // 0..1
    const int col  = tid & 63;        // 0..63
    const int clx  = col >> 2;        // cell 0..15
    const int x    = x0 + col;
    const int y0   = cellY * 4 + rp * 2;
    const float inv2sr2 = s_inv;

    const float ga0 = guid[(((size_t)b * 3 + 0) * HH + y0) * HH + x];
    const float ga1 = guid[(((size_t)b * 3 + 1) * HH + y0) * HH + x];
    const float ga2 = guid[(((size_t)b * 3 + 2) * HH + y0) * HH + x];
    const float gb0 = guid[(((size_t)b * 3 + 0) * HH + y0 + 1) * HH + x];
    const float gb1 = guid[(((size_t)b * 3 + 1) * HH + y0 + 1) * HH + x];
    const float gb2 = guid[(((size_t)b * 3 + 2) * HH + y0 + 1) * HH + x];

    float w0[25], w1[25];
    float den0 = 0.f, den1 = 0.f;
    #pragma unroll
    for (int dy = 0; dy < 5; dy++) {
        #pragma unroll
        for (int dx = 0; dx < 5; dx++) {
            const int t  = dy * 5 + dx;
            const int xl = clx + dx;
            float gl0 = s_gl[0][dy][xl];
            float gl1 = s_gl[1][dy][xl];
            float gl2 = s_gl[2][dy][xl];
            float d0 = ga0 - gl0, d1 = ga1 - gl1, d2 = ga2 - gl2;
            float e0 = gb0 - gl0, e1 = gb1 - gl1, e2 = gb2 - gl2;
            float diffa = d0 * d0 + d1 * d1 + d2 * d2;
            float diffb = e0 * e0 + e1 * e1 + e2 * e2;
            float sp2 = (float)((dy - 2) * (dy - 2) + (dx - 2) * (dx - 2)) * INV2SS2;
            float wa = __expf(-sp2 - diffa * inv2sr2);
            float wb = __expf(-sp2 - diffb * inv2sr2);
            w0[t] = wa; den0 += wa;
            w1[t] = wb; den1 += wb;
        }
    }
    const float inv0 = 1.0f / (den0 + 1e-8f);
    const float inv1 = 1.0f / (den1 + 1e-8f);

    unsigned long long wp[25];        // {w_row0, w_row1} per tap
    #pragma unroll
    for (int t = 0; t < 25; t++) {
        float a = w0[t] * inv0, c = w1[t] * inv1;
        asm("mov.b64 %0, {%1, %2};" : "=l"(wp[t]) : "f"(a), "f"(c));
    }

    // ---- phase 2: 16 channel-group iterations, 2 rows each via f32x2 ----
    const float4* ps = (const float4*)s_src + clx;
    #pragma unroll 1
    for (int cg = 0; cg < 16; cg++) {
        const float4* psi = ps + cg * ROWP;
        unsigned long long a0 = 0ULL, a1 = 0ULL, a2 = 0ULL, a3 = 0ULL;  // lanes = rows
        #pragma unroll
        for (int dy = 0; dy < 5; dy++) {
            #pragma unroll
            for (int dx = 0; dx < 5; dx++) {
                const int t = dy * 5 + dx;
                float4 sv = psi[dy * 20 + dx];        // 4 channels of this tap
                unsigned long long ss0, ss1, ss2, ss3;
                asm("mov.b64 %0, {%1, %1};" : "=l"(ss0) : "f"(sv.x));
                asm("mov.b64 %0, {%1, %1};" : "=l"(ss1) : "f"(sv.y));
                asm("mov.b64 %0, {%1, %1};" : "=l"(ss2) : "f"(sv.z));
                asm("mov.b64 %0, {%1, %1};" : "=l"(ss3) : "f"(sv.w));
                asm("fma.rn.f32x2 %0, %1, %2, %0;" : "+l"(a0) : "l"(wp[t]), "l"(ss0));
                asm("fma.rn.f32x2 %0, %1, %2, %0;" : "+l"(a1) : "l"(wp[t]), "l"(ss1));
                asm("fma.rn.f32x2 %0, %1, %2, %0;" : "+l"(a2) : "l"(wp[t]), "l"(ss2));
                asm("fma.rn.f32x2 %0, %1, %2, %0;" : "+l"(a3) : "l"(wp[t]), "l"(ss3));
            }
        }
        // store 4 channels x 2 rows
        #pragma unroll
        for (int c = 0; c < 4; c++) {
            unsigned long long a = (c == 0) ? a0 : (c == 1) ? a1 : (c == 2) ? a2 : a3;
            float lo, hi;
            asm("mov.b64 {%0, %1}, %2;" : "=f"(lo), "=f"(hi) : "l"(a));
            float* ob = out + (((size_t)(b * C_ + cg * 4 + c)) * HH + y0) * HH + x;
            ob[0]  = lo;      // row y0
            ob[HH] = hi;      // row y0+1
        }
    }
}

// ---------------- launch ----------------
extern "C" void kernel_launch(void* const* d_in, const int* in_sizes, int n_in,
                              void* d_out, int out_size) {
    const float* src  = (const float*)d_in[0];
    const float* guid = (const float*)d_in[1];
    if (n_in >= 2 && in_sizes[0] == B_ * GN) {
        const float* tmp = src; src = guid; guid = tmp;
    }
    float* out = (float*)d_out;

    jbu_pre<<<dim3(64, B_), 256>>>(guid);
    jbu_main<<<dim3(HH / 64, HH / 4, B_), 128>>>(guid, src, out);
}

// round 15
// speedup vs baseline: 1.6339x; 1.0077x over previous
#include <cuda_runtime.h>
#include <cstdint>

// Problem constants
#define B_   4
#define C_   64
#define HL   64      // low-res h = w
#define HH   256     // high-res H = W
#define NPIX (HH*HH)
#define GN   (3*HH*HH)
#define INV2SS2 0.08f        // 1/(2*2.5^2)

#define ROWP 101             // padded pos stride (float4 units) per channel plane

// ---------------- scratch ----------------
__device__ float g_part[B_][64][2];          // per-block partial (sum, sumsq)

// ---------------- pre-pass: guidance sum/sumsq partials ----------------
__global__ __launch_bounds__(256) void jbu_pre(const float* __restrict__ guid) {
    const int b   = blockIdx.y;
    const int tid = threadIdx.x;
    const float* p = guid + (size_t)b * GN + (size_t)blockIdx.x * (GN / 64);
    float s = 0.f, s2 = 0.f;
    for (int i = tid; i < GN / 64; i += 256) {
        float v = p[i];
        s += v; s2 += v * v;
    }
    #pragma unroll
    for (int o = 16; o; o >>= 1) {
        s  += __shfl_xor_sync(0xffffffffu, s,  o);
        s2 += __shfl_xor_sync(0xffffffffu, s2, o);
    }
    __shared__ float sh[8][2];
    const int w = tid >> 5;
    if ((tid & 31) == 0) { sh[w][0] = s; sh[w][1] = s2; }
    __syncthreads();
    if (tid == 0) {
        float ts = 0.f, ts2 = 0.f;
        #pragma unroll
        for (int i = 0; i < 8; i++) { ts += sh[i][0]; ts2 += sh[i][1]; }
        g_part[b][blockIdx.x][0] = ts;
        g_part[b][blockIdx.x][1] = ts2;
    }
}

// ---------------- main JBU kernel ----------------
// Block: 128 threads = (rp 0..1, col 0..63). Thread: 2 pixels (rows 2rp,2rp+1) x 64 ch.
// Tile: 4 rows x 64 cols. Grid: (HH/64=4, HH/4=64, B)
// Phase 2: chunk(4 cg) -> tap(25) -> cg(4); acc lanes = channel pairs (no source movs),
// weight splats {w,w} amortized 4x. launch_bounds(128,5): cap 102 regs, 5 CTA/SM.
__global__ __launch_bounds__(128, 5) void jbu_main(
    const float* __restrict__ guid,   // (4,3,256,256)
    const float* __restrict__ src,    // (4,64,64,64) raw channel-major
    float* __restrict__ out)          // (4,64,256,256)
{
    __shared__ __align__(16) float s_src[16 * ROWP * 4];   // [plane][pos] f4-interleaved
    __shared__ float s_gl[3][5][20];
    __shared__ float s_inv;

    const int b     = blockIdx.z;
    const int cellY = blockIdx.y;         // 0..63
    const int cx0   = blockIdx.x * 16;    // first low-res cell x
    const int x0    = cx0 * 4;

    const int tid = threadIdx.x;

    // ---- stage source tile straight from raw gmem ----
    for (int i = tid; i < 6400; i += 128) {
        int c   = i / 100;
        int pos = i - c * 100;
        int yl  = pos / 20, xl = pos - yl * 20;
        int yi  = min(max(cellY + yl - 2, 0), HL - 1);
        int xi  = min(max(cx0   + xl - 2, 0), HL - 1);
        float v = src[(((size_t)b * C_ + c) * HL + yi) * HL + xi];
        s_src[(((c >> 2) * ROWP) + pos) * 4 + (c & 3)] = v;
    }

    // ---- stage g_low tile ----
    for (int i = tid; i < 300; i += 128) {
        int c  = i / 100;
        int rm = i - c * 100;
        int yl = rm / 20, xl = rm - yl * 20;
        int yi = min(max(cellY + yl - 2, 0), HL - 1);
        int xi = min(max(cx0   + xl - 2, 0), HL - 1);
        s_gl[c][yl][xl] =
            guid[(((size_t)b * 3 + c) * HH + (4 * yi + 2)) * HH + (4 * xi + 2)];
    }

    // ---- sigma finalization (warp 0, deterministic double shfl-tree) ----
    if (tid < 32) {
        double s  = (double)g_part[b][2 * tid][0] + (double)g_part[b][2 * tid + 1][0];
        double s2 = (double)g_part[b][2 * tid][1] + (double)g_part[b][2 * tid + 1][1];
        #pragma unroll
        for (int o = 16; o; o >>= 1) {
            s  += __shfl_xor_sync(0xffffffffu, s,  o);
            s2 += __shfl_xor_sync(0xffffffffu, s2, o);
        }
        if (tid == 0) {
            const double N = (double)GN;
            double var = (s2 - s * s / N) / (N - 1.0);
            s_inv = (float)(2.0 / var);   // 1/(2*(0.5*sigma)^2) = 2/var
        }
    }
    __syncthreads();

    // ---- phase 1: normalized weights for BOTH rows (registers, floats) ----
    const int rp   = tid >> 6;        // 0..1
    const int col  = tid & 63;        // 0..63
    const int clx  = col >> 2;        // cell 0..15
    const int x    = x0 + col;
    const int y0   = cellY * 4 + rp * 2;
    const float inv2sr2 = s_inv;

    const float ga0 = guid[(((size_t)b * 3 + 0) * HH + y0) * HH + x];
    const float ga1 = guid[(((size_t)b * 3 + 1) * HH + y0) * HH + x];
    const float ga2 = guid[(((size_t)b * 3 + 2) * HH + y0) * HH + x];
    const float gb0 = guid[(((size_t)b * 3 + 0) * HH + y0 + 1) * HH + x];
    const float gb1 = guid[(((size_t)b * 3 + 1) * HH + y0 + 1) * HH + x];
    const float gb2 = guid[(((size_t)b * 3 + 2) * HH + y0 + 1) * HH + x];

    float w0[25], w1[25];
    float den0 = 0.f, den1 = 0.f;
    #pragma unroll
    for (int dy = 0; dy < 5; dy++) {
        #pragma unroll
        for (int dx = 0; dx < 5; dx++) {
            const int t  = dy * 5 + dx;
            const int xl = clx + dx;
            float gl0 = s_gl[0][dy][xl];
            float gl1 = s_gl[1][dy][xl];
            float gl2 = s_gl[2][dy][xl];
            float d0 = ga0 - gl0, d1 = ga1 - gl1, d2 = ga2 - gl2;
            float e0 = gb0 - gl0, e1 = gb1 - gl1, e2 = gb2 - gl2;
            float diffa = d0 * d0 + d1 * d1 + d2 * d2;
            float diffb = e0 * e0 + e1 * e1 + e2 * e2;
            float sp2 = (float)((dy - 2) * (dy - 2) + (dx - 2) * (dx - 2)) * INV2SS2;
            float wa = __expf(-sp2 - diffa * inv2sr2);
            float wb = __expf(-sp2 - diffb * inv2sr2);
            w0[t] = wa; den0 += wa;
            w1[t] = wb; den1 += wb;
        }
    }
    const float inv0 = 1.0f / (den0 + 1e-8f);
    const float inv1 = 1.0f / (den1 + 1e-8f);
    #pragma unroll
    for (int t = 0; t < 25; t++) { w0[t] *= inv0; w1[t] *= inv1; }

    // ---- phase 2: 4 chunks x (25 taps x 4 cg) ----
    const ulonglong2* ps = (const ulonglong2*)s_src + clx;
    #pragma unroll 1
    for (int cgc = 0; cgc < 4; cgc++) {
        const ulonglong2* psc = ps + (cgc * 4) * ROWP;

        // per cg i: aA[i]={r0:c0,c1}, aB[i]={r0:c2,c3}, bA[i]={r1:c0,c1}, bB[i]={r1:c2,c3}
        unsigned long long aA[4], aB[4], bA[4], bB[4];
        #pragma unroll
        for (int i = 0; i < 4; i++) { aA[i] = 0ULL; aB[i] = 0ULL; bA[i] = 0ULL; bB[i] = 0ULL; }

        #pragma unroll
        for (int dy = 0; dy < 5; dy++) {
            #pragma unroll
            for (int dx = 0; dx < 5; dx++) {
                const int t = dy * 5 + dx;
                unsigned long long wax, wbx;
                asm("mov.b64 %0, {%1, %1};" : "=l"(wax) : "f"(w0[t]));
                asm("mov.b64 %0, {%1, %1};" : "=l"(wbx) : "f"(w1[t]));
                #pragma unroll
                for (int i = 0; i < 4; i++) {
                    ulonglong2 sv = psc[i * ROWP + dy * 20 + dx];   // {c0,c1},{c2,c3}
                    asm("fma.rn.f32x2 %0, %1, %2, %0;" : "+l"(aA[i]) : "l"(wax), "l"(sv.x));
                    asm("fma.rn.f32x2 %0, %1, %2, %0;" : "+l"(aB[i]) : "l"(wax), "l"(sv.y));
                    asm("fma.rn.f32x2 %0, %1, %2, %0;" : "+l"(bA[i]) : "l"(wbx), "l"(sv.x));
                    asm("fma.rn.f32x2 %0, %1, %2, %0;" : "+l"(bB[i]) : "l"(wbx), "l"(sv.y));
                }
            }
        }

        // stores: 4 cg x 4 channels x 2 rows
        #pragma unroll
        for (int i = 0; i < 4; i++) {
            const int ch0 = (cgc * 4 + i) * 4;
            float v0, v1, v2, v3, u0, u1, u2, u3;
            asm("mov.b64 {%0, %1}, %2;" : "=f"(v0), "=f"(v1) : "l"(aA[i]));
            asm("mov.b64 {%0, %1}, %2;" : "=f"(v2), "=f"(v3) : "l"(aB[i]));
            asm("mov.b64 {%0, %1}, %2;" : "=f"(u0), "=f"(u1) : "l"(bA[i]));
            asm("mov.b64 {%0, %1}, %2;" : "=f"(u2), "=f"(u3) : "l"(bB[i]));
            float* ob = out + (((size_t)(b * C_ + ch0)) * HH + y0) * HH + x;
            ob[0 * (size_t)NPIX]      = v0;
            ob[1 * (size_t)NPIX]      = v1;
            ob[2 * (size_t)NPIX]      = v2;
            ob[3 * (size_t)NPIX]      = v3;
            ob[0 * (size_t)NPIX + HH] = u0;
            ob[1 * (size_t)NPIX + HH] = u1;
            ob[2 * (size_t)NPIX + HH] = u2;
            ob[3 * (size_t)NPIX + HH] = u3;
        }
    }
}

// ---------------- launch ----------------
extern "C" void kernel_launch(void* const* d_in, const int* in_sizes, int n_in,
                              void* d_out, int out_size) {
    const float* src  = (const float*)d_in[0];
    const float* guid = (const float*)d_in[1];
    if (n_in >= 2 && in_sizes[0] == B_ * GN) {
        const float* tmp = src; src = guid; guid = tmp;
    }
    float* out = (float*)d_out;

    jbu_pre<<<dim3(64, B_), 256>>>(guid);
    jbu_main<<<dim3(HH / 64, HH / 4, B_), 128>>>(guid, src, out);
}